// round 12
// baseline (speedup 1.0000x reference)
#include <cuda_runtime.h>
#include <cstdint>
#include <cstddef>

#define Nn 50000
#define Ee 1600000
#define Gg 128
#define Hh 64

typedef unsigned long long ull;

// ---- scratch (device globals) ----
__device__ float g_z[(size_t)5 * Nn * Hh];     // 64 MB: z_k = segment_sum(ea_k * act(h[src]))
__device__ float g_h0[(size_t)Nn * Hh];        // ping
__device__ float g_h1[(size_t)Nn * Hh];        // pong
__device__ float g_pool[Gg * 2 * Hh];

// dst-CSR sort scratch (24 B/edge, split)
__device__ int    g_cnt[Nn];
__device__ int    g_cursor[Nn];
__device__ int    g_rowptr[Nn + 1];
__device__ float4 g_er0[Ee];                   // {src, w0, w1, w2}
__device__ float2 g_er1[Ee];                   // {w3, w4}

// ============================================================
// counting sort by dst: hist -> scan -> permute
// ============================================================
__global__ void zero_cnt_kernel(int* __restrict__ cnt)
{
    unsigned i = blockIdx.x * 256u + threadIdx.x;
    if (i < (unsigned)Nn) cnt[i] = 0;
}

__global__ void hist_kernel(const int* __restrict__ ei, int* __restrict__ cnt)
{
    unsigned e = blockIdx.x * 256u + threadIdx.x;
    if (e < (unsigned)Ee) atomicAdd(&cnt[__ldg(ei + Ee + e)], 1);  // dst
}

__global__ void scan_kernel(const int* __restrict__ cnt,
                            int* __restrict__ cursor,
                            int* __restrict__ rowptr)
{
    __shared__ int tsum[1024];
    const int t  = threadIdx.x;
    const int CH = (Nn + 1023) / 1024;  // 49
    const int base = t * CH;

    int s = 0;
#pragma unroll 1
    for (int i = 0; i < CH; ++i) {
        int idx = base + i;
        if (idx < Nn) s += cnt[idx];
    }
    tsum[t] = s;
    __syncthreads();
    for (int o = 1; o < 1024; o <<= 1) {
        int u = (t >= o) ? tsum[t - o] : 0;
        __syncthreads();
        tsum[t] += u;
        __syncthreads();
    }
    int run = tsum[t] - s;  // exclusive
#pragma unroll 1
    for (int i = 0; i < CH; ++i) {
        int idx = base + i;
        if (idx < Nn) {
            cursor[idx] = run;
            rowptr[idx] = run;
            run += cnt[idx];
        }
    }
    if (t == 0) rowptr[Nn] = Ee;
}

__global__ void permute_kernel(const int* __restrict__ ei,
                               const float* __restrict__ ea,
                               int* __restrict__ cursor,
                               float4* __restrict__ er0,
                               float2* __restrict__ er1)
{
    unsigned e = blockIdx.x * 256u + threadIdx.x;
    if (e >= (unsigned)Ee) return;
    int src = __ldg(ei + e);
    int dst = __ldg(ei + Ee + e);
    const float* p = ea + (size_t)e * 5;
    float w0 = __ldg(p), w1 = __ldg(p + 1), w2 = __ldg(p + 2),
          w3 = __ldg(p + 3), w4 = __ldg(p + 4);
    int pos = atomicAdd(&cursor[dst], 1);
    er0[pos] = make_float4(__int_as_float(src), w0, w1, w2);
    er1[pos] = make_float2(w3, w4);
}

// ============================================================
// Aggregate (H=64): one warp per dst node; 2 edges in flight.
// Lanes 0-15 process even edges, 16-31 odd edges; each lane = 4 feats
// (float4 gather). Halves combined via shfl_xor(16) at the end.
// ============================================================
__global__ void aggregate64_kernel(const int* __restrict__ rowptr,
                                   const float4* __restrict__ er0,
                                   const float2* __restrict__ er1,
                                   const float* __restrict__ x,
                                   float* __restrict__ z)
{
    int dst = blockIdx.x * 8 + (threadIdx.x >> 5);
    if (dst >= Nn) return;
    const int lane = threadIdx.x & 31;
    const int hl   = lane & 15;   // feat group: feats 4*hl..4*hl+3
    const int par  = lane >> 4;   // edge parity
    const int beg = __ldg(rowptr + dst);
    const int end = __ldg(rowptr + dst + 1);

    float4 a0 = {0.f,0.f,0.f,0.f}, a1 = a0, a2 = a0, a3 = a0, a4 = a0;

#pragma unroll 2
    for (int e = beg + par; e < end; e += 2) {
        float4 r0 = __ldg(er0 + e);
        float2 r1 = __ldg(er1 + e);
        int src = __float_as_int(r0.x);
        float4 v = __ldg((const float4*)(x + (size_t)src * 64 + hl * 4));
        a0.x += r0.y*v.x; a0.y += r0.y*v.y; a0.z += r0.y*v.z; a0.w += r0.y*v.w;
        a1.x += r0.z*v.x; a1.y += r0.z*v.y; a1.z += r0.z*v.z; a1.w += r0.z*v.w;
        a2.x += r0.w*v.x; a2.y += r0.w*v.y; a2.z += r0.w*v.z; a2.w += r0.w*v.w;
        a3.x += r1.x*v.x; a3.y += r1.x*v.y; a3.z += r1.x*v.z; a3.w += r1.x*v.w;
        a4.x += r1.y*v.x; a4.y += r1.y*v.y; a4.z += r1.y*v.z; a4.w += r1.y*v.w;
    }

    // combine parity halves (same feats live at lane and lane^16)
#define CMB(f) f += __shfl_xor_sync(0xffffffffu, f, 16)
    CMB(a0.x); CMB(a0.y); CMB(a0.z); CMB(a0.w);
    CMB(a1.x); CMB(a1.y); CMB(a1.z); CMB(a1.w);
    CMB(a2.x); CMB(a2.y); CMB(a2.z); CMB(a2.w);
    CMB(a3.x); CMB(a3.y); CMB(a3.z); CMB(a3.w);
    CMB(a4.x); CMB(a4.y); CMB(a4.z); CMB(a4.w);
#undef CMB

    if (par == 0) {
        const size_t KS = (size_t)Nn * 64;
        float* zp = z + (size_t)dst * 64 + hl * 4;
        *(float4*)(zp)        = a0;
        *(float4*)(zp + KS)   = a1;
        *(float4*)(zp + 2*KS) = a2;
        *(float4*)(zp + 3*KS) = a3;
        *(float4*)(zp + 4*KS) = a4;
    }
}

// ============================================================
// Aggregate (F=16, layer 1, raw x): warp splits in 2 halves over edges.
// ============================================================
__global__ void aggregate16_kernel(const int* __restrict__ rowptr,
                                   const float4* __restrict__ er0,
                                   const float2* __restrict__ er1,
                                   const float* __restrict__ x,
                                   float* __restrict__ z)
{
    int dst = blockIdx.x * 8 + (threadIdx.x >> 5);
    if (dst >= Nn) return;
    const int lane = threadIdx.x & 31;
    const int half = lane >> 4;
    const int f    = lane & 15;
    const int beg = __ldg(rowptr + dst);
    const int end = __ldg(rowptr + dst + 1);

    float a0 = 0.f, a1 = 0.f, a2 = 0.f, a3 = 0.f, a4 = 0.f;

    for (int e = beg + half; e < end; e += 2) {
        float4 r0 = __ldg(er0 + e);
        float2 r1 = __ldg(er1 + e);
        int src = __float_as_int(r0.x);
        float v = __ldg(x + (size_t)src * 16 + f);
        a0 += r0.y * v; a1 += r0.z * v; a2 += r0.w * v;
        a3 += r1.x * v; a4 += r1.y * v;
    }
    a0 += __shfl_xor_sync(0xffffffffu, a0, 16);
    a1 += __shfl_xor_sync(0xffffffffu, a1, 16);
    a2 += __shfl_xor_sync(0xffffffffu, a2, 16);
    a3 += __shfl_xor_sync(0xffffffffu, a3, 16);
    a4 += __shfl_xor_sync(0xffffffffu, a4, 16);

    if (half == 0) {
        const size_t KS = (size_t)Nn * 16;
        float* zp = z + (size_t)dst * 16 + f;
        zp[0]    = a0;
        zp[KS]   = a1;
        zp[2*KS] = a2;
        zp[3*KS] = a3;
        zp[4*KS] = a4;
    }
}

// ============================================================
// GEMM-sum: h[n] = relu( sum_k z_k[n] @ W[k] + b )
// 128 nodes x 64 outs / CTA, 256 threads; acc = 4 node-pairs x 4 cols
// of f32x2. W staged DUPLICATED in smem ((w,w) pairs) so the inner
// loop has zero packing movs: 4 LDS.128 + 16 fma.rn.f32x2 per kk.
// Dynamic smem: zsT[KD][132] + ws2[KD][128]. 3 CTAs/SM (KD=64).
// ============================================================
template<int KD>
__global__ void __launch_bounds__(256, 3)
gemmsum_kernel(const float* __restrict__ z,
               const float* __restrict__ W,
               const float* __restrict__ b,
               float* __restrict__ h)
{
    extern __shared__ float smem[];
    float* zsT = smem;               // [KD][132], node-major rows
    float* ws2 = smem + KD * 132;    // [KD][128]: col c duplicated at 2c,2c+1

    const int t  = threadIdx.x;
    const int n0 = blockIdx.x * 128;
    const int tx = t & 15;           // cols 4tx..4tx+3
    const int ty = t >> 4;           // nodes ty*8..ty*8+7 (4 pairs)

    ull acc[4][4];                   // [node-pair][col] of (even,odd) f32x2
#pragma unroll
    for (int p = 0; p < 4; ++p)
#pragma unroll
        for (int c = 0; c < 4; ++c) acc[p][c] = 0ull;

#pragma unroll 1
    for (int k = 0; k < 5; ++k) {
        __syncthreads();
        const float* zk = z + (size_t)k * Nn * KD;
        for (int idx = t; idx < 128 * KD; idx += 256) {
            int node = idx / KD;
            int c    = idx - node * KD;
            int n    = n0 + node;
            zsT[c * 132 + node] = (n < Nn) ? zk[(size_t)n * KD + c] : 0.f;
        }
        for (int idx = t; idx < KD * 64; idx += 256) {
            float w = __ldg(W + k * KD * 64 + idx);
            int kk = idx >> 6;
            int c  = idx & 63;
            *(float2*)&ws2[kk * 128 + c * 2] = make_float2(w, w);
        }
        __syncthreads();

#pragma unroll 8
        for (int kk = 0; kk < KD; ++kk) {
            // 8 nodes = 4 (even,odd) pairs, loaded directly as f32x2
            ull2_t: ;
            const ull* xp = (const ull*)&zsT[kk * 132 + ty * 8];
            ull x0 = xp[0], x1 = xp[1], x2 = xp[2], x3 = xp[3];
            // 4 duplicated w pairs: (w0,w0),(w1,w1),(w2,w2),(w3,w3)
            const ull* wp = (const ull*)&ws2[kk * 128 + tx * 8];
            ull w0 = wp[0], w1 = wp[1], w2 = wp[2], w3 = wp[3];
#define FMA2(a, xv, wv) asm("fma.rn.f32x2 %0,%1,%2,%0;" : "+l"(a) : "l"(xv), "l"(wv))
            FMA2(acc[0][0], x0, w0); FMA2(acc[0][1], x0, w1);
            FMA2(acc[0][2], x0, w2); FMA2(acc[0][3], x0, w3);
            FMA2(acc[1][0], x1, w0); FMA2(acc[1][1], x1, w1);
            FMA2(acc[1][2], x1, w2); FMA2(acc[1][3], x1, w3);
            FMA2(acc[2][0], x2, w0); FMA2(acc[2][1], x2, w1);
            FMA2(acc[2][2], x2, w2); FMA2(acc[2][3], x2, w3);
            FMA2(acc[3][0], x3, w0); FMA2(acc[3][1], x3, w1);
            FMA2(acc[3][2], x3, w2); FMA2(acc[3][3], x3, w3);
#undef FMA2
        }
    }

    float4 bb = *(const float4*)&b[tx * 4];
#pragma unroll
    for (int p = 0; p < 4; ++p) {
        // unpack: acc[p][c] = (h[n_even][c], h[n_odd][c])
        float e0, o0, e1, o1, e2, o2, e3, o3;
        asm("mov.b64 {%0,%1},%2;" : "=f"(e0), "=f"(o0) : "l"(acc[p][0]));
        asm("mov.b64 {%0,%1},%2;" : "=f"(e1), "=f"(o1) : "l"(acc[p][1]));
        asm("mov.b64 {%0,%1},%2;" : "=f"(e2), "=f"(o2) : "l"(acc[p][2]));
        asm("mov.b64 {%0,%1},%2;" : "=f"(e3), "=f"(o3) : "l"(acc[p][3]));
        int ne = n0 + ty * 8 + p * 2;
        if (ne < Nn) {
            float4 oe;
            oe.x = fmaxf(e0 + bb.x, 0.f);
            oe.y = fmaxf(e1 + bb.y, 0.f);
            oe.z = fmaxf(e2 + bb.z, 0.f);
            oe.w = fmaxf(e3 + bb.w, 0.f);
            *(float4*)&h[(size_t)ne * 64 + tx * 4] = oe;
        }
        if (ne + 1 < Nn) {
            float4 oo;
            oo.x = fmaxf(o0 + bb.x, 0.f);
            oo.y = fmaxf(o1 + bb.y, 0.f);
            oo.z = fmaxf(o2 + bb.z, 0.f);
            oo.w = fmaxf(o3 + bb.w, 0.f);
            *(float4*)&h[(size_t)(ne + 1) * 64 + tx * 4] = oo;
        }
    }
}

// ============================================================
// Pooling: h already relu'd; sum & max per analytic graph ranges.
// ============================================================
__global__ void pool_kernel(const float* __restrict__ h, float* __restrict__ pooled)
{
    __shared__ float ss[4][64];
    __shared__ float sm[4][64];
    int g     = blockIdx.x;
    int f     = threadIdx.x & 63;
    int strip = threadIdx.x >> 6;
    int start = (g * Nn + Gg - 1) / Gg;
    int end   = ((g + 1) * Nn + Gg - 1) / Gg;

    float s = 0.f, m = 0.f;  // h >= 0
    for (int n = start + strip; n < end; n += 4) {
        float v = __ldg(h + (size_t)n * 64 + f);
        s += v;
        m = fmaxf(m, v);
    }
    ss[strip][f] = s;
    sm[strip][f] = m;
    __syncthreads();
    if (strip == 0) {
        s = ss[0][f] + ss[1][f] + ss[2][f] + ss[3][f];
        m = fmaxf(fmaxf(sm[0][f], sm[1][f]), fmaxf(sm[2][f], sm[3][f]));
        pooled[g * 128 + f]      = s;
        pooled[g * 128 + 64 + f] = m;
    }
}

// ============================================================
// Head: BN -> FC -> log_softmax
// ============================================================
__global__ void head_kernel(const float* __restrict__ pooled,
                            const float* __restrict__ gam,
                            const float* __restrict__ bet,
                            const float* __restrict__ mean,
                            const float* __restrict__ var,
                            const float* __restrict__ fw,
                            const float* __restrict__ fb,
                            float* __restrict__ out)
{
    int g    = blockIdx.x;
    int lane = threadIdx.x;

    float pn[4];
#pragma unroll
    for (int i = 0; i < 4; ++i) {
        int c = lane + 32 * i;
        float p = __ldg(pooled + g * 128 + c);
        float inv = 1.f / sqrtf(__ldg(var + c) + 1e-5f);
        pn[i] = (p - __ldg(mean + c)) * inv * __ldg(gam + c) + __ldg(bet + c);
    }

    float logits[6];
#pragma unroll
    for (int j = 0; j < 6; ++j) {
        float s = 0.f;
#pragma unroll
        for (int i = 0; i < 4; ++i)
            s += pn[i] * __ldg(fw + (lane + 32 * i) * 6 + j);
#pragma unroll
        for (int o = 16; o; o >>= 1)
            s += __shfl_xor_sync(0xffffffffu, s, o);
        logits[j] = s + __ldg(fb + j);
    }

    if (lane == 0) {
        float m = logits[0];
#pragma unroll
        for (int j = 1; j < 6; ++j) m = fmaxf(m, logits[j]);
        float se = 0.f;
#pragma unroll
        for (int j = 0; j < 6; ++j) se += expf(logits[j] - m);
        float lse = m + logf(se);
#pragma unroll
        for (int j = 0; j < 6; ++j) out[g * 6 + j] = logits[j] - lse;
    }
}

// ============================================================
extern "C" void kernel_launch(void* const* d_in, const int* in_sizes, int n_in,
                              void* d_out, int out_size)
{
    const float* x   = (const float*)d_in[0];
    const int*   ei  = (const int*)  d_in[1];
    const float* ea  = (const float*)d_in[2];
    const float* W1  = (const float*)d_in[4];
    const float* b1  = (const float*)d_in[5];
    const float* W2  = (const float*)d_in[6];
    const float* b2  = (const float*)d_in[7];
    const float* W3  = (const float*)d_in[8];
    const float* b3  = (const float*)d_in[9];
    const float* W4  = (const float*)d_in[10];
    const float* b4  = (const float*)d_in[11];
    const float* bng = (const float*)d_in[12];
    const float* bnb = (const float*)d_in[13];
    const float* bnm = (const float*)d_in[14];
    const float* bnv = (const float*)d_in[15];
    const float* fw  = (const float*)d_in[16];
    const float* fb  = (const float*)d_in[17];
    float* out = (float*)d_out;

    float *zb, *h0, *h1, *pl;
    int *cnt, *cur, *rp;
    float4* er0;
    float2* er1;
    cudaGetSymbolAddress((void**)&zb, g_z);
    cudaGetSymbolAddress((void**)&h0, g_h0);
    cudaGetSymbolAddress((void**)&h1, g_h1);
    cudaGetSymbolAddress((void**)&pl, g_pool);
    cudaGetSymbolAddress((void**)&cnt, g_cnt);
    cudaGetSymbolAddress((void**)&cur, g_cursor);
    cudaGetSymbolAddress((void**)&rp, g_rowptr);
    cudaGetSymbolAddress((void**)&er0, g_er0);
    cudaGetSymbolAddress((void**)&er1, g_er1);

    const int EB = (Ee + 255) / 256;        // 6250
    const int GB = (Nn + 127) / 128;        // 391
    const int AB = (Nn + 7) / 8;            // 6250 (one warp per dst)

    const int SM16 = (16 * 132 + 16 * 128) * 4;   // 16640 B
    const int SM64 = (64 * 132 + 64 * 128) * 4;   // 66560 B
    static int smem_set = 0;
    if (!smem_set) {
        cudaFuncSetAttribute(gemmsum_kernel<16>, cudaFuncAttributeMaxDynamicSharedMemorySize, SM16);
        cudaFuncSetAttribute(gemmsum_kernel<64>, cudaFuncAttributeMaxDynamicSharedMemorySize, SM64);
        smem_set = 1;
    }

    // ---- counting sort of edges by dst -> CSR ----
    zero_cnt_kernel<<<(Nn + 255) / 256, 256>>>(cnt);
    hist_kernel<<<EB, 256>>>(ei, cnt);
    scan_kernel<<<1, 1024>>>(cnt, cur, rp);
    permute_kernel<<<EB, 256>>>(ei, ea, cur, er0, er1);

    // ---- layer 1 (in: x [N,16], raw) ----
    aggregate16_kernel<<<AB, 256>>>(rp, er0, er1, x, zb);
    gemmsum_kernel<16><<<GB, 256, SM16>>>(zb, W1, b1, h0);
    // ---- layer 2 ----
    aggregate64_kernel<<<AB, 256>>>(rp, er0, er1, h0, zb);
    gemmsum_kernel<64><<<GB, 256, SM64>>>(zb, W2, b2, h1);
    // ---- layer 3 ----
    aggregate64_kernel<<<AB, 256>>>(rp, er0, er1, h1, zb);
    gemmsum_kernel<64><<<GB, 256, SM64>>>(zb, W3, b3, h0);
    // ---- layer 4 ----
    aggregate64_kernel<<<AB, 256>>>(rp, er0, er1, h0, zb);
    gemmsum_kernel<64><<<GB, 256, SM64>>>(zb, W4, b4, h1);

    pool_kernel<<<Gg, 256>>>(h1, pl);
    head_kernel<<<Gg, 32>>>(pl, bng, bnb, bnm, bnv, fw, fb, out);
}

// round 13
// speedup vs baseline: 1.2026x; 1.2026x over previous
#include <cuda_runtime.h>
#include <cstdint>
#include <cstddef>

#define Nn 50000
#define Ee 1600000
#define Gg 128
#define Hh 64

typedef unsigned long long ull;

// ---- scratch (device globals) ----
__device__ float g_z[(size_t)5 * Nn * Hh];     // 64 MB: z_k = segment_sum(ea_k * act(h[src]))
__device__ float g_h0[(size_t)Nn * Hh];        // ping
__device__ float g_h1[(size_t)Nn * Hh];        // pong
__device__ float g_pool[Gg * 2 * Hh];

// dst-CSR sort scratch (24 B/edge, split)
__device__ int    g_cnt[Nn];
__device__ int    g_cursor[Nn];
__device__ int    g_rowptr[Nn + 1];
__device__ float4 g_er0[Ee];                   // {src, w0, w1, w2}
__device__ float2 g_er1[Ee];                   // {w3, w4}

// ============================================================
// counting sort by dst: hist -> scan -> permute
// ============================================================
__global__ void zero_cnt_kernel(int* __restrict__ cnt)
{
    unsigned i = blockIdx.x * 256u + threadIdx.x;
    if (i < (unsigned)Nn) cnt[i] = 0;
}

__global__ void hist_kernel(const int* __restrict__ ei, int* __restrict__ cnt)
{
    unsigned e = blockIdx.x * 256u + threadIdx.x;
    if (e < (unsigned)Ee) atomicAdd(&cnt[__ldg(ei + Ee + e)], 1);  // dst
}

__global__ void scan_kernel(const int* __restrict__ cnt,
                            int* __restrict__ cursor,
                            int* __restrict__ rowptr)
{
    __shared__ int tsum[1024];
    const int t  = threadIdx.x;
    const int CH = (Nn + 1023) / 1024;  // 49
    const int base = t * CH;

    int s = 0;
#pragma unroll 1
    for (int i = 0; i < CH; ++i) {
        int idx = base + i;
        if (idx < Nn) s += cnt[idx];
    }
    tsum[t] = s;
    __syncthreads();
    for (int o = 1; o < 1024; o <<= 1) {
        int u = (t >= o) ? tsum[t - o] : 0;
        __syncthreads();
        tsum[t] += u;
        __syncthreads();
    }
    int run = tsum[t] - s;  // exclusive
#pragma unroll 1
    for (int i = 0; i < CH; ++i) {
        int idx = base + i;
        if (idx < Nn) {
            cursor[idx] = run;
            rowptr[idx] = run;
            run += cnt[idx];
        }
    }
    if (t == 0) rowptr[Nn] = Ee;
}

__global__ void permute_kernel(const int* __restrict__ ei,
                               const float* __restrict__ ea,
                               int* __restrict__ cursor,
                               float4* __restrict__ er0,
                               float2* __restrict__ er1)
{
    unsigned e = blockIdx.x * 256u + threadIdx.x;
    if (e >= (unsigned)Ee) return;
    int src = __ldg(ei + e);
    int dst = __ldg(ei + Ee + e);
    const float* p = ea + (size_t)e * 5;
    float w0 = __ldg(p), w1 = __ldg(p + 1), w2 = __ldg(p + 2),
          w3 = __ldg(p + 3), w4 = __ldg(p + 4);
    int pos = atomicAdd(&cursor[dst], 1);
    er0[pos] = make_float4(__int_as_float(src), w0, w1, w2);
    er1[pos] = make_float2(w3, w4);
}

// ============================================================
// Aggregate (H=64): one warp per dst node; 2 edges in flight.
// Lanes 0-15 process even edges, 16-31 odd edges; each lane = 4 feats
// (float4 gather). Halves combined via shfl_xor(16) at the end.
// ============================================================
__global__ void aggregate64_kernel(const int* __restrict__ rowptr,
                                   const float4* __restrict__ er0,
                                   const float2* __restrict__ er1,
                                   const float* __restrict__ x,
                                   float* __restrict__ z)
{
    int dst = blockIdx.x * 8 + (threadIdx.x >> 5);
    if (dst >= Nn) return;
    const int lane = threadIdx.x & 31;
    const int hl   = lane & 15;   // feat group: feats 4*hl..4*hl+3
    const int par  = lane >> 4;   // edge parity
    const int beg = __ldg(rowptr + dst);
    const int end = __ldg(rowptr + dst + 1);

    float4 a0 = {0.f,0.f,0.f,0.f}, a1 = a0, a2 = a0, a3 = a0, a4 = a0;

#pragma unroll 2
    for (int e = beg + par; e < end; e += 2) {
        float4 r0 = __ldg(er0 + e);
        float2 r1 = __ldg(er1 + e);
        int src = __float_as_int(r0.x);
        float4 v = __ldg((const float4*)(x + (size_t)src * 64 + hl * 4));
        a0.x += r0.y*v.x; a0.y += r0.y*v.y; a0.z += r0.y*v.z; a0.w += r0.y*v.w;
        a1.x += r0.z*v.x; a1.y += r0.z*v.y; a1.z += r0.z*v.z; a1.w += r0.z*v.w;
        a2.x += r0.w*v.x; a2.y += r0.w*v.y; a2.z += r0.w*v.z; a2.w += r0.w*v.w;
        a3.x += r1.x*v.x; a3.y += r1.x*v.y; a3.z += r1.x*v.z; a3.w += r1.x*v.w;
        a4.x += r1.y*v.x; a4.y += r1.y*v.y; a4.z += r1.y*v.z; a4.w += r1.y*v.w;
    }

    // combine parity halves (same feats live at lane and lane^16)
#define CMB(f) f += __shfl_xor_sync(0xffffffffu, f, 16)
    CMB(a0.x); CMB(a0.y); CMB(a0.z); CMB(a0.w);
    CMB(a1.x); CMB(a1.y); CMB(a1.z); CMB(a1.w);
    CMB(a2.x); CMB(a2.y); CMB(a2.z); CMB(a2.w);
    CMB(a3.x); CMB(a3.y); CMB(a3.z); CMB(a3.w);
    CMB(a4.x); CMB(a4.y); CMB(a4.z); CMB(a4.w);
#undef CMB

    if (par == 0) {
        const size_t KS = (size_t)Nn * 64;
        float* zp = z + (size_t)dst * 64 + hl * 4;
        *(float4*)(zp)        = a0;
        *(float4*)(zp + KS)   = a1;
        *(float4*)(zp + 2*KS) = a2;
        *(float4*)(zp + 3*KS) = a3;
        *(float4*)(zp + 4*KS) = a4;
    }
}

// ============================================================
// Aggregate (F=16, layer 1, raw x): warp splits in 2 halves over edges.
// ============================================================
__global__ void aggregate16_kernel(const int* __restrict__ rowptr,
                                   const float4* __restrict__ er0,
                                   const float2* __restrict__ er1,
                                   const float* __restrict__ x,
                                   float* __restrict__ z)
{
    int dst = blockIdx.x * 8 + (threadIdx.x >> 5);
    if (dst >= Nn) return;
    const int lane = threadIdx.x & 31;
    const int half = lane >> 4;
    const int f    = lane & 15;
    const int beg = __ldg(rowptr + dst);
    const int end = __ldg(rowptr + dst + 1);

    float a0 = 0.f, a1 = 0.f, a2 = 0.f, a3 = 0.f, a4 = 0.f;

    for (int e = beg + half; e < end; e += 2) {
        float4 r0 = __ldg(er0 + e);
        float2 r1 = __ldg(er1 + e);
        int src = __float_as_int(r0.x);
        float v = __ldg(x + (size_t)src * 16 + f);
        a0 += r0.y * v; a1 += r0.z * v; a2 += r0.w * v;
        a3 += r1.x * v; a4 += r1.y * v;
    }
    a0 += __shfl_xor_sync(0xffffffffu, a0, 16);
    a1 += __shfl_xor_sync(0xffffffffu, a1, 16);
    a2 += __shfl_xor_sync(0xffffffffu, a2, 16);
    a3 += __shfl_xor_sync(0xffffffffu, a3, 16);
    a4 += __shfl_xor_sync(0xffffffffu, a4, 16);

    if (half == 0) {
        const size_t KS = (size_t)Nn * 16;
        float* zp = z + (size_t)dst * 16 + f;
        zp[0]    = a0;
        zp[KS]   = a1;
        zp[2*KS] = a2;
        zp[3*KS] = a3;
        zp[4*KS] = a4;
    }
}

// ============================================================
// GEMM-sum: h[n] = relu( sum_k z_k[n] @ W[k] + b )
// 128 nodes x 64 outs / CTA, 256 threads; acc = 4 node-pairs x 4 cols
// of f32x2. x loaded directly as packed node-pairs from zsT (zero movs);
// W kept plain in smem, duplicated via 4 movs per kk.
// Dynamic smem: zsT[KD][132] + ws[KD*64] = 50 KB (KD=64). 4 CTAs/SM.
// ============================================================
template<int KD>
__global__ void __launch_bounds__(256, 4)
gemmsum_kernel(const float* __restrict__ z,
               const float* __restrict__ W,
               const float* __restrict__ b,
               float* __restrict__ h)
{
    extern __shared__ float smem[];
    float* zsT = smem;               // [KD][132], node-major rows
    float* ws  = smem + KD * 132;    // [KD*64]

    const int t  = threadIdx.x;
    const int n0 = blockIdx.x * 128;
    const int tx = t & 15;           // cols 4tx..4tx+3
    const int ty = t >> 4;           // nodes ty*8..ty*8+7 (4 pairs)

    ull acc[4][4];                   // [node-pair][col] of (even,odd) f32x2
#pragma unroll
    for (int p = 0; p < 4; ++p)
#pragma unroll
        for (int c = 0; c < 4; ++c) acc[p][c] = 0ull;

#pragma unroll 1
    for (int k = 0; k < 5; ++k) {
        __syncthreads();
        const float* zk = z + (size_t)k * Nn * KD;
        for (int idx = t; idx < 128 * KD; idx += 256) {
            int node = idx / KD;
            int c    = idx - node * KD;
            int n    = n0 + node;
            zsT[c * 132 + node] = (n < Nn) ? zk[(size_t)n * KD + c] : 0.f;
        }
        for (int idx = t; idx < KD * 64; idx += 256)
            ws[idx] = __ldg(W + k * KD * 64 + idx);
        __syncthreads();

#pragma unroll 8
        for (int kk = 0; kk < KD; ++kk) {
            // 8 nodes = 4 (even,odd) pairs, loaded directly as packed f32x2
            const ull* xp = (const ull*)&zsT[kk * 132 + ty * 8];
            ull x0 = xp[0], x1 = xp[1], x2 = xp[2], x3 = xp[3];
            // 4 cols, duplicated into (w,w) pairs via 4 movs
            float4 wv = *(const float4*)&ws[kk * 64 + tx * 4];
            ull w0, w1, w2, w3;
            asm("mov.b64 %0,{%1,%1};" : "=l"(w0) : "f"(wv.x));
            asm("mov.b64 %0,{%1,%1};" : "=l"(w1) : "f"(wv.y));
            asm("mov.b64 %0,{%1,%1};" : "=l"(w2) : "f"(wv.z));
            asm("mov.b64 %0,{%1,%1};" : "=l"(w3) : "f"(wv.w));
#define FMA2(a, xv, wvv) asm("fma.rn.f32x2 %0,%1,%2,%0;" : "+l"(a) : "l"(xv), "l"(wvv))
            FMA2(acc[0][0], x0, w0); FMA2(acc[0][1], x0, w1);
            FMA2(acc[0][2], x0, w2); FMA2(acc[0][3], x0, w3);
            FMA2(acc[1][0], x1, w0); FMA2(acc[1][1], x1, w1);
            FMA2(acc[1][2], x1, w2); FMA2(acc[1][3], x1, w3);
            FMA2(acc[2][0], x2, w0); FMA2(acc[2][1], x2, w1);
            FMA2(acc[2][2], x2, w2); FMA2(acc[2][3], x2, w3);
            FMA2(acc[3][0], x3, w0); FMA2(acc[3][1], x3, w1);
            FMA2(acc[3][2], x3, w2); FMA2(acc[3][3], x3, w3);
#undef FMA2
        }
    }

    float4 bb = *(const float4*)&b[tx * 4];
#pragma unroll
    for (int p = 0; p < 4; ++p) {
        // unpack: acc[p][c] = (h[n_even][c], h[n_odd][c])
        float e0, o0, e1, o1, e2, o2, e3, o3;
        asm("mov.b64 {%0,%1},%2;" : "=f"(e0), "=f"(o0) : "l"(acc[p][0]));
        asm("mov.b64 {%0,%1},%2;" : "=f"(e1), "=f"(o1) : "l"(acc[p][1]));
        asm("mov.b64 {%0,%1},%2;" : "=f"(e2), "=f"(o2) : "l"(acc[p][2]));
        asm("mov.b64 {%0,%1},%2;" : "=f"(e3), "=f"(o3) : "l"(acc[p][3]));
        int ne = n0 + ty * 8 + p * 2;
        if (ne < Nn) {
            float4 oe;
            oe.x = fmaxf(e0 + bb.x, 0.f);
            oe.y = fmaxf(e1 + bb.y, 0.f);
            oe.z = fmaxf(e2 + bb.z, 0.f);
            oe.w = fmaxf(e3 + bb.w, 0.f);
            *(float4*)&h[(size_t)ne * 64 + tx * 4] = oe;
        }
        if (ne + 1 < Nn) {
            float4 oo;
            oo.x = fmaxf(o0 + bb.x, 0.f);
            oo.y = fmaxf(o1 + bb.y, 0.f);
            oo.z = fmaxf(o2 + bb.z, 0.f);
            oo.w = fmaxf(o3 + bb.w, 0.f);
            *(float4*)&h[(size_t)(ne + 1) * 64 + tx * 4] = oo;
        }
    }
}

// ============================================================
// Pooling: h already relu'd; sum & max per analytic graph ranges.
// ============================================================
__global__ void pool_kernel(const float* __restrict__ h, float* __restrict__ pooled)
{
    __shared__ float ss[4][64];
    __shared__ float sm[4][64];
    int g     = blockIdx.x;
    int f     = threadIdx.x & 63;
    int strip = threadIdx.x >> 6;
    int start = (g * Nn + Gg - 1) / Gg;
    int end   = ((g + 1) * Nn + Gg - 1) / Gg;

    float s = 0.f, m = 0.f;  // h >= 0
    for (int n = start + strip; n < end; n += 4) {
        float v = __ldg(h + (size_t)n * 64 + f);
        s += v;
        m = fmaxf(m, v);
    }
    ss[strip][f] = s;
    sm[strip][f] = m;
    __syncthreads();
    if (strip == 0) {
        s = ss[0][f] + ss[1][f] + ss[2][f] + ss[3][f];
        m = fmaxf(fmaxf(sm[0][f], sm[1][f]), fmaxf(sm[2][f], sm[3][f]));
        pooled[g * 128 + f]      = s;
        pooled[g * 128 + 64 + f] = m;
    }
}

// ============================================================
// Head: BN -> FC -> log_softmax
// ============================================================
__global__ void head_kernel(const float* __restrict__ pooled,
                            const float* __restrict__ gam,
                            const float* __restrict__ bet,
                            const float* __restrict__ mean,
                            const float* __restrict__ var,
                            const float* __restrict__ fw,
                            const float* __restrict__ fb,
                            float* __restrict__ out)
{
    int g    = blockIdx.x;
    int lane = threadIdx.x;

    float pn[4];
#pragma unroll
    for (int i = 0; i < 4; ++i) {
        int c = lane + 32 * i;
        float p = __ldg(pooled + g * 128 + c);
        float inv = 1.f / sqrtf(__ldg(var + c) + 1e-5f);
        pn[i] = (p - __ldg(mean + c)) * inv * __ldg(gam + c) + __ldg(bet + c);
    }

    float logits[6];
#pragma unroll
    for (int j = 0; j < 6; ++j) {
        float s = 0.f;
#pragma unroll
        for (int i = 0; i < 4; ++i)
            s += pn[i] * __ldg(fw + (lane + 32 * i) * 6 + j);
#pragma unroll
        for (int o = 16; o; o >>= 1)
            s += __shfl_xor_sync(0xffffffffu, s, o);
        logits[j] = s + __ldg(fb + j);
    }

    if (lane == 0) {
        float m = logits[0];
#pragma unroll
        for (int j = 1; j < 6; ++j) m = fmaxf(m, logits[j]);
        float se = 0.f;
#pragma unroll
        for (int j = 0; j < 6; ++j) se += expf(logits[j] - m);
        float lse = m + logf(se);
#pragma unroll
        for (int j = 0; j < 6; ++j) out[g * 6 + j] = logits[j] - lse;
    }
}

// ============================================================
extern "C" void kernel_launch(void* const* d_in, const int* in_sizes, int n_in,
                              void* d_out, int out_size)
{
    const float* x   = (const float*)d_in[0];
    const int*   ei  = (const int*)  d_in[1];
    const float* ea  = (const float*)d_in[2];
    const float* W1  = (const float*)d_in[4];
    const float* b1  = (const float*)d_in[5];
    const float* W2  = (const float*)d_in[6];
    const float* b2  = (const float*)d_in[7];
    const float* W3  = (const float*)d_in[8];
    const float* b3  = (const float*)d_in[9];
    const float* W4  = (const float*)d_in[10];
    const float* b4  = (const float*)d_in[11];
    const float* bng = (const float*)d_in[12];
    const float* bnb = (const float*)d_in[13];
    const float* bnm = (const float*)d_in[14];
    const float* bnv = (const float*)d_in[15];
    const float* fw  = (const float*)d_in[16];
    const float* fb  = (const float*)d_in[17];
    float* out = (float*)d_out;

    float *zb, *h0, *h1, *pl;
    int *cnt, *cur, *rp;
    float4* er0;
    float2* er1;
    cudaGetSymbolAddress((void**)&zb, g_z);
    cudaGetSymbolAddress((void**)&h0, g_h0);
    cudaGetSymbolAddress((void**)&h1, g_h1);
    cudaGetSymbolAddress((void**)&pl, g_pool);
    cudaGetSymbolAddress((void**)&cnt, g_cnt);
    cudaGetSymbolAddress((void**)&cur, g_cursor);
    cudaGetSymbolAddress((void**)&rp, g_rowptr);
    cudaGetSymbolAddress((void**)&er0, g_er0);
    cudaGetSymbolAddress((void**)&er1, g_er1);

    const int EB = (Ee + 255) / 256;        // 6250
    const int GB = (Nn + 127) / 128;        // 391
    const int AB = (Nn + 7) / 8;            // 6250 (one warp per dst)

    const int SM16 = (16 * 132 + 16 * 64) * 4;   // 12544 B
    const int SM64 = (64 * 132 + 64 * 64) * 4;   // 50176 B
    static int smem_set = 0;
    if (!smem_set) {
        cudaFuncSetAttribute(gemmsum_kernel<16>, cudaFuncAttributeMaxDynamicSharedMemorySize, SM16);
        cudaFuncSetAttribute(gemmsum_kernel<64>, cudaFuncAttributeMaxDynamicSharedMemorySize, SM64);
        smem_set = 1;
    }

    // ---- counting sort of edges by dst -> CSR ----
    zero_cnt_kernel<<<(Nn + 255) / 256, 256>>>(cnt);
    hist_kernel<<<EB, 256>>>(ei, cnt);
    scan_kernel<<<1, 1024>>>(cnt, cur, rp);
    permute_kernel<<<EB, 256>>>(ei, ea, cur, er0, er1);

    // ---- layer 1 (in: x [N,16], raw) ----
    aggregate16_kernel<<<AB, 256>>>(rp, er0, er1, x, zb);
    gemmsum_kernel<16><<<GB, 256, SM16>>>(zb, W1, b1, h0);
    // ---- layer 2 ----
    aggregate64_kernel<<<AB, 256>>>(rp, er0, er1, h0, zb);
    gemmsum_kernel<64><<<GB, 256, SM64>>>(zb, W2, b2, h1);
    // ---- layer 3 ----
    aggregate64_kernel<<<AB, 256>>>(rp, er0, er1, h1, zb);
    gemmsum_kernel<64><<<GB, 256, SM64>>>(zb, W3, b3, h0);
    // ---- layer 4 ----
    aggregate64_kernel<<<AB, 256>>>(rp, er0, er1, h0, zb);
    gemmsum_kernel<64><<<GB, 256, SM64>>>(zb, W4, b4, h1);

    pool_kernel<<<Gg, 256>>>(h1, pl);
    head_kernel<<<Gg, 32>>>(pl, bng, bnb, bnm, bnv, fw, fb, out);
}

// round 14
// speedup vs baseline: 1.3588x; 1.1298x over previous
#include <cuda_runtime.h>
#include <cstdint>
#include <cstddef>

#define Nn 50000
#define Ee 1600000
#define Gg 128
#define Hh 64

typedef unsigned long long ull;

// ---- scratch (device globals) ----
__device__ float g_z[(size_t)5 * Nn * Hh];     // 64 MB: z_k = segment_sum(ea_k * act(h[src]))
__device__ float g_h0[(size_t)Nn * Hh];        // ping
__device__ float g_h1[(size_t)Nn * Hh];        // pong
__device__ float g_pool[Gg * 2 * Hh];

// dst-CSR sort scratch (24 B/edge, split)
__device__ int    g_cnt[Nn];
__device__ int    g_cursor[Nn];
__device__ int    g_rowptr[Nn + 1];
__device__ float4 g_er0[Ee];                   // {src, w0, w1, w2}
__device__ float2 g_er1[Ee];                   // {w3, w4}

// ============================================================
// counting sort by dst: hist -> scan -> permute
// ============================================================
__global__ void zero_cnt_kernel(int* __restrict__ cnt)
{
    unsigned i = blockIdx.x * 256u + threadIdx.x;
    if (i < (unsigned)Nn) cnt[i] = 0;
}

__global__ void hist_kernel(const int* __restrict__ ei, int* __restrict__ cnt)
{
    unsigned e = blockIdx.x * 256u + threadIdx.x;
    if (e < (unsigned)Ee) atomicAdd(&cnt[__ldg(ei + Ee + e)], 1);  // dst
}

__global__ void scan_kernel(const int* __restrict__ cnt,
                            int* __restrict__ cursor,
                            int* __restrict__ rowptr)
{
    __shared__ int tsum[1024];
    const int t  = threadIdx.x;
    const int CH = (Nn + 1023) / 1024;  // 49
    const int base = t * CH;

    int s = 0;
#pragma unroll 1
    for (int i = 0; i < CH; ++i) {
        int idx = base + i;
        if (idx < Nn) s += cnt[idx];
    }
    tsum[t] = s;
    __syncthreads();
    for (int o = 1; o < 1024; o <<= 1) {
        int u = (t >= o) ? tsum[t - o] : 0;
        __syncthreads();
        tsum[t] += u;
        __syncthreads();
    }
    int run = tsum[t] - s;  // exclusive
#pragma unroll 1
    for (int i = 0; i < CH; ++i) {
        int idx = base + i;
        if (idx < Nn) {
            cursor[idx] = run;
            rowptr[idx] = run;
            run += cnt[idx];
        }
    }
    if (t == 0) rowptr[Nn] = Ee;
}

__global__ void permute_kernel(const int* __restrict__ ei,
                               const float* __restrict__ ea,
                               int* __restrict__ cursor,
                               float4* __restrict__ er0,
                               float2* __restrict__ er1)
{
    unsigned e = blockIdx.x * 256u + threadIdx.x;
    if (e >= (unsigned)Ee) return;
    int src = __ldg(ei + e);
    int dst = __ldg(ei + Ee + e);
    const float* p = ea + (size_t)e * 5;
    float w0 = __ldg(p), w1 = __ldg(p + 1), w2 = __ldg(p + 2),
          w3 = __ldg(p + 3), w4 = __ldg(p + 4);
    int pos = atomicAdd(&cursor[dst], 1);
    er0[pos] = make_float4(__int_as_float(src), w0, w1, w2);
    er1[pos] = make_float2(w3, w4);
}

// ============================================================
// Aggregate (H=64): one warp per dst node; 2 edges in flight.
// ============================================================
__global__ void aggregate64_kernel(const int* __restrict__ rowptr,
                                   const float4* __restrict__ er0,
                                   const float2* __restrict__ er1,
                                   const float* __restrict__ x,
                                   float* __restrict__ z)
{
    int dst = blockIdx.x * 8 + (threadIdx.x >> 5);
    if (dst >= Nn) return;
    const int lane = threadIdx.x & 31;
    const int hl   = lane & 15;   // feat group: feats 4*hl..4*hl+3
    const int par  = lane >> 4;   // edge parity
    const int beg = __ldg(rowptr + dst);
    const int end = __ldg(rowptr + dst + 1);

    float4 a0 = {0.f,0.f,0.f,0.f}, a1 = a0, a2 = a0, a3 = a0, a4 = a0;

#pragma unroll 2
    for (int e = beg + par; e < end; e += 2) {
        float4 r0 = __ldg(er0 + e);
        float2 r1 = __ldg(er1 + e);
        int src = __float_as_int(r0.x);
        float4 v = __ldg((const float4*)(x + (size_t)src * 64 + hl * 4));
        a0.x += r0.y*v.x; a0.y += r0.y*v.y; a0.z += r0.y*v.z; a0.w += r0.y*v.w;
        a1.x += r0.z*v.x; a1.y += r0.z*v.y; a1.z += r0.z*v.z; a1.w += r0.z*v.w;
        a2.x += r0.w*v.x; a2.y += r0.w*v.y; a2.z += r0.w*v.z; a2.w += r0.w*v.w;
        a3.x += r1.x*v.x; a3.y += r1.x*v.y; a3.z += r1.x*v.z; a3.w += r1.x*v.w;
        a4.x += r1.y*v.x; a4.y += r1.y*v.y; a4.z += r1.y*v.z; a4.w += r1.y*v.w;
    }

#define CMB(f) f += __shfl_xor_sync(0xffffffffu, f, 16)
    CMB(a0.x); CMB(a0.y); CMB(a0.z); CMB(a0.w);
    CMB(a1.x); CMB(a1.y); CMB(a1.z); CMB(a1.w);
    CMB(a2.x); CMB(a2.y); CMB(a2.z); CMB(a2.w);
    CMB(a3.x); CMB(a3.y); CMB(a3.z); CMB(a3.w);
    CMB(a4.x); CMB(a4.y); CMB(a4.z); CMB(a4.w);
#undef CMB

    if (par == 0) {
        const size_t KS = (size_t)Nn * 64;
        float* zp = z + (size_t)dst * 64 + hl * 4;
        *(float4*)(zp)        = a0;
        *(float4*)(zp + KS)   = a1;
        *(float4*)(zp + 2*KS) = a2;
        *(float4*)(zp + 3*KS) = a3;
        *(float4*)(zp + 4*KS) = a4;
    }
}

// ============================================================
// Aggregate (F=16, layer 1, raw x)
// ============================================================
__global__ void aggregate16_kernel(const int* __restrict__ rowptr,
                                   const float4* __restrict__ er0,
                                   const float2* __restrict__ er1,
                                   const float* __restrict__ x,
                                   float* __restrict__ z)
{
    int dst = blockIdx.x * 8 + (threadIdx.x >> 5);
    if (dst >= Nn) return;
    const int lane = threadIdx.x & 31;
    const int half = lane >> 4;
    const int f    = lane & 15;
    const int beg = __ldg(rowptr + dst);
    const int end = __ldg(rowptr + dst + 1);

    float a0 = 0.f, a1 = 0.f, a2 = 0.f, a3 = 0.f, a4 = 0.f;

    for (int e = beg + half; e < end; e += 2) {
        float4 r0 = __ldg(er0 + e);
        float2 r1 = __ldg(er1 + e);
        int src = __float_as_int(r0.x);
        float v = __ldg(x + (size_t)src * 16 + f);
        a0 += r0.y * v; a1 += r0.z * v; a2 += r0.w * v;
        a3 += r1.x * v; a4 += r1.y * v;
    }
    a0 += __shfl_xor_sync(0xffffffffu, a0, 16);
    a1 += __shfl_xor_sync(0xffffffffu, a1, 16);
    a2 += __shfl_xor_sync(0xffffffffu, a2, 16);
    a3 += __shfl_xor_sync(0xffffffffu, a3, 16);
    a4 += __shfl_xor_sync(0xffffffffu, a4, 16);

    if (half == 0) {
        const size_t KS = (size_t)Nn * 16;
        float* zp = z + (size_t)dst * 16 + f;
        zp[0]    = a0;
        zp[KS]   = a1;
        zp[2*KS] = a2;
        zp[3*KS] = a3;
        zp[4*KS] = a4;
    }
}

// ============================================================
// Tensor-core GEMM-sum: h[n] = relu( sum_k z_k[n] @ W[k] + b )
// mma.sync.m16n8k8 tf32, fp32 accumulate. 128 nodes x 64 cols / CTA,
// 8 warps, warp tile 32x32 (warp grid 4x2). Operands converted to
// tf32 at smem staging. smem: zs[128][ZPAD] + ws[KD][72] u32.
// KD=64: 53.2 KB -> 4 CTAs/SM.
// ============================================================
template<int KD>
__global__ void __launch_bounds__(256, 4)
gemmsum_kernel(const float* __restrict__ z,
               const float* __restrict__ W,
               const float* __restrict__ b,
               float* __restrict__ h)
{
    constexpr int ZPAD = (KD == 64) ? 68 : 20;
    constexpr int WPAD = 72;
    extern __shared__ uint32_t smu[];
    uint32_t* zs = smu;                 // [128][ZPAD] tf32 bits
    uint32_t* ws = smu + 128 * ZPAD;    // [KD][WPAD]  tf32 bits

    const int t    = threadIdx.x;
    const int warp = t >> 5;
    const int lane = t & 31;
    const int gid  = lane >> 2;    // 0..7
    const int tig  = lane & 3;     // 0..3
    const int wm   = warp >> 1;    // 0..3 -> m offset 32*wm
    const int wn   = warp & 1;     // 0..1 -> n offset 32*wn
    const int n0   = blockIdx.x * 128;

    float acc[2][4][4];
#pragma unroll
    for (int mf = 0; mf < 2; ++mf)
#pragma unroll
        for (int nf = 0; nf < 4; ++nf)
#pragma unroll
            for (int r = 0; r < 4; ++r) acc[mf][nf][r] = 0.f;

#pragma unroll 1
    for (int k = 0; k < 5; ++k) {
        __syncthreads();
        const float* zk = z + (size_t)k * Nn * KD;
        for (int idx = t; idx < 128 * KD; idx += 256) {
            int node = idx / KD;
            int c    = idx - node * KD;
            int n    = n0 + node;
            float v  = (n < Nn) ? zk[(size_t)n * KD + c] : 0.f;
            uint32_t u;
            asm("cvt.rna.tf32.f32 %0, %1;" : "=r"(u) : "f"(v));
            zs[node * ZPAD + c] = u;
        }
        for (int idx = t; idx < KD * 64; idx += 256) {
            float v = __ldg(W + k * KD * 64 + idx);
            uint32_t u;
            asm("cvt.rna.tf32.f32 %0, %1;" : "=r"(u) : "f"(v));
            int kk = idx >> 6;
            int c  = idx & 63;
            ws[kk * WPAD + c] = u;
        }
        __syncthreads();

#pragma unroll
        for (int kb = 0; kb < KD; kb += 8) {
            uint32_t a[2][4];
#pragma unroll
            for (int mf = 0; mf < 2; ++mf) {
                int row = wm * 32 + mf * 16 + gid;
                a[mf][0] = zs[row * ZPAD + kb + tig];
                a[mf][1] = zs[(row + 8) * ZPAD + kb + tig];
                a[mf][2] = zs[row * ZPAD + kb + tig + 4];
                a[mf][3] = zs[(row + 8) * ZPAD + kb + tig + 4];
            }
            uint32_t bf[4][2];
#pragma unroll
            for (int nf = 0; nf < 4; ++nf) {
                int col = wn * 32 + nf * 8 + gid;
                bf[nf][0] = ws[(kb + tig) * WPAD + col];
                bf[nf][1] = ws[(kb + tig + 4) * WPAD + col];
            }
#pragma unroll
            for (int mf = 0; mf < 2; ++mf)
#pragma unroll
                for (int nf = 0; nf < 4; ++nf) {
                    asm volatile(
                        "mma.sync.aligned.m16n8k8.row.col.f32.tf32.tf32.f32 "
                        "{%0,%1,%2,%3}, {%4,%5,%6,%7}, {%8,%9}, {%0,%1,%2,%3};"
                        : "+f"(acc[mf][nf][0]), "+f"(acc[mf][nf][1]),
                          "+f"(acc[mf][nf][2]), "+f"(acc[mf][nf][3])
                        : "r"(a[mf][0]), "r"(a[mf][1]), "r"(a[mf][2]), "r"(a[mf][3]),
                          "r"(bf[nf][0]), "r"(bf[nf][1]));
                }
        }
    }

    // epilogue: bias + relu + store (c0,c1 are cols 2*tig,2*tig+1 of frag)
#pragma unroll
    for (int mf = 0; mf < 2; ++mf) {
#pragma unroll
        for (int nf = 0; nf < 4; ++nf) {
            int col = wn * 32 + nf * 8 + 2 * tig;
            float bx = __ldg(b + col);
            float by = __ldg(b + col + 1);
            int row = n0 + wm * 32 + mf * 16 + gid;
            if (row < Nn) {
                float2 o;
                o.x = fmaxf(acc[mf][nf][0] + bx, 0.f);
                o.y = fmaxf(acc[mf][nf][1] + by, 0.f);
                *(float2*)&h[(size_t)row * 64 + col] = o;
            }
            int row2 = row + 8;
            if (row2 < Nn) {
                float2 o;
                o.x = fmaxf(acc[mf][nf][2] + bx, 0.f);
                o.y = fmaxf(acc[mf][nf][3] + by, 0.f);
                *(float2*)&h[(size_t)row2 * 64 + col] = o;
            }
        }
    }
}

// ============================================================
// Pooling: h already relu'd; sum & max per analytic graph ranges.
// ============================================================
__global__ void pool_kernel(const float* __restrict__ h, float* __restrict__ pooled)
{
    __shared__ float ss[4][64];
    __shared__ float sm[4][64];
    int g     = blockIdx.x;
    int f     = threadIdx.x & 63;
    int strip = threadIdx.x >> 6;
    int start = (g * Nn + Gg - 1) / Gg;
    int end   = ((g + 1) * Nn + Gg - 1) / Gg;

    float s = 0.f, m = 0.f;  // h >= 0
    for (int n = start + strip; n < end; n += 4) {
        float v = __ldg(h + (size_t)n * 64 + f);
        s += v;
        m = fmaxf(m, v);
    }
    ss[strip][f] = s;
    sm[strip][f] = m;
    __syncthreads();
    if (strip == 0) {
        s = ss[0][f] + ss[1][f] + ss[2][f] + ss[3][f];
        m = fmaxf(fmaxf(sm[0][f], sm[1][f]), fmaxf(sm[2][f], sm[3][f]));
        pooled[g * 128 + f]      = s;
        pooled[g * 128 + 64 + f] = m;
    }
}

// ============================================================
// Head: BN -> FC -> log_softmax
// ============================================================
__global__ void head_kernel(const float* __restrict__ pooled,
                            const float* __restrict__ gam,
                            const float* __restrict__ bet,
                            const float* __restrict__ mean,
                            const float* __restrict__ var,
                            const float* __restrict__ fw,
                            const float* __restrict__ fb,
                            float* __restrict__ out)
{
    int g    = blockIdx.x;
    int lane = threadIdx.x;

    float pn[4];
#pragma unroll
    for (int i = 0; i < 4; ++i) {
        int c = lane + 32 * i;
        float p = __ldg(pooled + g * 128 + c);
        float inv = 1.f / sqrtf(__ldg(var + c) + 1e-5f);
        pn[i] = (p - __ldg(mean + c)) * inv * __ldg(gam + c) + __ldg(bet + c);
    }

    float logits[6];
#pragma unroll
    for (int j = 0; j < 6; ++j) {
        float s = 0.f;
#pragma unroll
        for (int i = 0; i < 4; ++i)
            s += pn[i] * __ldg(fw + (lane + 32 * i) * 6 + j);
#pragma unroll
        for (int o = 16; o; o >>= 1)
            s += __shfl_xor_sync(0xffffffffu, s, o);
        logits[j] = s + __ldg(fb + j);
    }

    if (lane == 0) {
        float m = logits[0];
#pragma unroll
        for (int j = 1; j < 6; ++j) m = fmaxf(m, logits[j]);
        float se = 0.f;
#pragma unroll
        for (int j = 0; j < 6; ++j) se += expf(logits[j] - m);
        float lse = m + logf(se);
#pragma unroll
        for (int j = 0; j < 6; ++j) out[g * 6 + j] = logits[j] - lse;
    }
}

// ============================================================
extern "C" void kernel_launch(void* const* d_in, const int* in_sizes, int n_in,
                              void* d_out, int out_size)
{
    const float* x   = (const float*)d_in[0];
    const int*   ei  = (const int*)  d_in[1];
    const float* ea  = (const float*)d_in[2];
    const float* W1  = (const float*)d_in[4];
    const float* b1  = (const float*)d_in[5];
    const float* W2  = (const float*)d_in[6];
    const float* b2  = (const float*)d_in[7];
    const float* W3  = (const float*)d_in[8];
    const float* b3  = (const float*)d_in[9];
    const float* W4  = (const float*)d_in[10];
    const float* b4  = (const float*)d_in[11];
    const float* bng = (const float*)d_in[12];
    const float* bnb = (const float*)d_in[13];
    const float* bnm = (const float*)d_in[14];
    const float* bnv = (const float*)d_in[15];
    const float* fw  = (const float*)d_in[16];
    const float* fb  = (const float*)d_in[17];
    float* out = (float*)d_out;

    float *zb, *h0, *h1, *pl;
    int *cnt, *cur, *rp;
    float4* er0;
    float2* er1;
    cudaGetSymbolAddress((void**)&zb, g_z);
    cudaGetSymbolAddress((void**)&h0, g_h0);
    cudaGetSymbolAddress((void**)&h1, g_h1);
    cudaGetSymbolAddress((void**)&pl, g_pool);
    cudaGetSymbolAddress((void**)&cnt, g_cnt);
    cudaGetSymbolAddress((void**)&cur, g_cursor);
    cudaGetSymbolAddress((void**)&rp, g_rowptr);
    cudaGetSymbolAddress((void**)&er0, g_er0);
    cudaGetSymbolAddress((void**)&er1, g_er1);

    const int EB = (Ee + 255) / 256;        // 6250
    const int GB = (Nn + 127) / 128;        // 391
    const int AB = (Nn + 7) / 8;            // 6250 (one warp per dst)

    const int SM16 = (128 * 20 + 16 * 72) * 4;   // 14848 B
    const int SM64 = (128 * 68 + 64 * 72) * 4;   // 53248 B
    static int smem_set = 0;
    if (!smem_set) {
        cudaFuncSetAttribute(gemmsum_kernel<16>, cudaFuncAttributeMaxDynamicSharedMemorySize, SM16);
        cudaFuncSetAttribute(gemmsum_kernel<64>, cudaFuncAttributeMaxDynamicSharedMemorySize, SM64);
        smem_set = 1;
    }

    // ---- counting sort of edges by dst -> CSR ----
    zero_cnt_kernel<<<(Nn + 255) / 256, 256>>>(cnt);
    hist_kernel<<<EB, 256>>>(ei, cnt);
    scan_kernel<<<1, 1024>>>(cnt, cur, rp);
    permute_kernel<<<EB, 256>>>(ei, ea, cur, er0, er1);

    // ---- layer 1 (in: x [N,16], raw) ----
    aggregate16_kernel<<<AB, 256>>>(rp, er0, er1, x, zb);
    gemmsum_kernel<16><<<GB, 256, SM16>>>(zb, W1, b1, h0);
    // ---- layer 2 ----
    aggregate64_kernel<<<AB, 256>>>(rp, er0, er1, h0, zb);
    gemmsum_kernel<64><<<GB, 256, SM64>>>(zb, W2, b2, h1);
    // ---- layer 3 ----
    aggregate64_kernel<<<AB, 256>>>(rp, er0, er1, h1, zb);
    gemmsum_kernel<64><<<GB, 256, SM64>>>(zb, W3, b3, h0);
    // ---- layer 4 ----
    aggregate64_kernel<<<AB, 256>>>(rp, er0, er1, h0, zb);
    gemmsum_kernel<64><<<GB, 256, SM64>>>(zb, W4, b4, h1);

    pool_kernel<<<Gg, 256>>>(h1, pl);
    head_kernel<<<Gg, 32>>>(pl, bng, bnb, bnm, bnv, fw, fb, out);
}